// round 1
// baseline (speedup 1.0000x reference)
#include <cuda_runtime.h>
#include <cuda_bf16.h>
#include <math.h>

#define GAMMA_J 5.828427124746190f   // 3 + 2*sqrt(2)
#define CSTAR   0.923879532511287f   // cos(pi/8)
#define SSTAR   0.3826834323650897f  // sin(pi/8)
#define QR_EPS  1e-12f
#define DEG2RAD 0.017453292519943295f
#define SIGMA_MIN 0.05f
#define NORM_EPS 1e-10f

#define BLOCK 256

__device__ __forceinline__ void condSwap(bool c, float &X, float &Y) {
    float Z = X;
    X = c ? Y : X;
    Y = c ? Z : Y;
}
__device__ __forceinline__ void condNegSwap(bool c, float &X, float &Y) {
    float Z = -X;
    X = c ? Y : X;
    Y = c ? Z : Y;
}

// Approximate Givens quaternion (McAdams et al.)
__device__ __forceinline__ void approxGivens(float a11, float a12, float a22,
                                             float &ch, float &sh) {
    ch = 2.0f * (a11 - a22);
    sh = a12;
    bool b = GAMMA_J * sh * sh < ch * ch;
    float w = rsqrtf(ch * ch + sh * sh);
    ch = b ? w * ch : CSTAR;
    sh = b ? w * sh : SSTAR;
}

// One Jacobi conjugation step with cyclic permutation. x,y,z are literal
// constants at every call site -> q[] stays in registers.
__device__ __forceinline__ void jacobiConj(const int x, const int y, const int z,
    float &s11, float &s21, float &s22, float &s31, float &s32, float &s33,
    float *q) {
    float ch, sh;
    approxGivens(s11, s21, s22, ch, sh);
    // (ch,sh) is ~unit; skip the /(ch^2+sh^2) division (error ~1e-7, only
    // affects S scaling, not V quality; sigma comes from QR of A*V).
    float a = ch * ch - sh * sh;
    float b = 2.0f * sh * ch;

    float _s11 = s11, _s21 = s21, _s22 = s22, _s31 = s31, _s32 = s32, _s33 = s33;
    s11 = a * (a * _s11 + b * _s21) + b * (a * _s21 + b * _s22);
    s21 = a * (-b * _s11 + a * _s21) + b * (-b * _s21 + a * _s22);
    s22 = -b * (-b * _s11 + a * _s21) + a * (-b * _s21 + a * _s22);
    s31 = a * _s31 + b * _s32;
    s32 = -b * _s31 + a * _s32;
    s33 = _s33;

    // accumulate rotation into quaternion
    float tmp[3];
    tmp[0] = q[0] * sh;
    tmp[1] = q[1] * sh;
    tmp[2] = q[2] * sh;
    sh *= q[3];
    q[0] *= ch; q[1] *= ch; q[2] *= ch; q[3] *= ch;
    q[z] += sh;
    q[3] -= tmp[z];
    q[x] += tmp[y];
    q[y] -= tmp[x];

    // cyclic re-arrangement for next pivot
    _s11 = s22; _s21 = s32; _s22 = s33;
    _s31 = s21; _s32 = s31; _s33 = s11;
    s11 = _s11; s21 = _s21; s22 = _s22;
    s31 = _s31; s32 = _s32; s33 = _s33;
}

__device__ __forceinline__ void qrGivens(float a1, float a2, float &ch, float &sh) {
    float rho = sqrtf(a1 * a1 + a2 * a2);
    sh = rho > QR_EPS ? a2 : 0.0f;
    ch = fabsf(a1) + fmaxf(rho, QR_EPS);
    bool b = a1 < 0.0f;
    condSwap(b, sh, ch);
    float w = rsqrtf(ch * ch + sh * sh);
    ch *= w;
    sh *= w;
}

__global__ void __launch_bounds__(BLOCK)
dp_plasticity_kernel(const float* __restrict__ F,
                     const float* __restrict__ ylog_p,
                     const float* __restrict__ nu_p,
                     const float* __restrict__ phi_p,
                     const float* __restrict__ coh_p,
                     float* __restrict__ out, int n) {
    __shared__ float sm[BLOCK * 9];

    const int tid  = threadIdx.x;
    const int base = blockIdx.x * BLOCK;
    const int cnt  = min(BLOCK, n - base);          // matrices in this block
    const int nflt = cnt * 9;

    // ---- coalesced load: global -> smem ----
    if (cnt == BLOCK) {
        const float4* gv = (const float4*)(F + (size_t)base * 9);
        float4* sv = (float4*)sm;
        #pragma unroll
        for (int k = tid; k < BLOCK * 9 / 4; k += BLOCK) sv[k] = gv[k];
    } else {
        const float* g = F + (size_t)base * 9;
        for (int k = tid; k < nflt; k += BLOCK) sm[k] = g[k];
    }
    __syncthreads();

    if (tid < cnt) {
        const float* a = sm + tid * 9;
        float a11 = a[0], a12 = a[1], a13 = a[2];
        float a21 = a[3], a22 = a[4], a23 = a[5];
        float a31 = a[6], a32 = a[7], a33 = a[8];

        // ---- S = A^T A (symmetric) ----
        float s11 = a11 * a11 + a21 * a21 + a31 * a31;
        float s21 = a11 * a12 + a21 * a22 + a31 * a32;
        float s22 = a12 * a12 + a22 * a22 + a32 * a32;
        float s31 = a11 * a13 + a21 * a23 + a31 * a33;
        float s32 = a12 * a13 + a22 * a23 + a32 * a33;
        float s33 = a13 * a13 + a23 * a23 + a33 * a33;

        // ---- Jacobi eigenanalysis (4 sweeps) -> quaternion ----
        float q[4] = {0.0f, 0.0f, 0.0f, 1.0f};
        #pragma unroll
        for (int sweep = 0; sweep < 4; sweep++) {
            jacobiConj(0, 1, 2, s11, s21, s22, s31, s32, s33, q);
            jacobiConj(1, 2, 0, s11, s21, s22, s31, s32, s33, q);
            jacobiConj(2, 0, 1, s11, s21, s22, s31, s32, s33, q);
        }

        // ---- quaternion -> V (normalize first) ----
        float qs = rsqrtf(q[0] * q[0] + q[1] * q[1] + q[2] * q[2] + q[3] * q[3]);
        float qx = q[0] * qs, qy = q[1] * qs, qz = q[2] * qs, qw = q[3] * qs;
        float v11 = 1.0f - 2.0f * (qy * qy + qz * qz);
        float v12 = 2.0f * (qx * qy - qw * qz);
        float v13 = 2.0f * (qx * qz + qw * qy);
        float v21 = 2.0f * (qx * qy + qw * qz);
        float v22 = 1.0f - 2.0f * (qx * qx + qz * qz);
        float v23 = 2.0f * (qy * qz - qw * qx);
        float v31 = 2.0f * (qx * qz - qw * qy);
        float v32 = 2.0f * (qy * qz + qw * qx);
        float v33 = 1.0f - 2.0f * (qx * qx + qy * qy);

        // ---- B = A * V ----
        float b11 = a11 * v11 + a12 * v21 + a13 * v31;
        float b12 = a11 * v12 + a12 * v22 + a13 * v32;
        float b13 = a11 * v13 + a12 * v23 + a13 * v33;
        float b21 = a21 * v11 + a22 * v21 + a23 * v31;
        float b22 = a21 * v12 + a22 * v22 + a23 * v32;
        float b23 = a21 * v13 + a22 * v23 + a23 * v33;
        float b31 = a31 * v11 + a32 * v21 + a33 * v31;
        float b32 = a31 * v12 + a32 * v22 + a33 * v32;
        float b33 = a31 * v13 + a32 * v23 + a33 * v33;

        // ---- sort columns of B (and V) by norm, preserving orientation ----
        float rho1 = b11 * b11 + b21 * b21 + b31 * b31;
        float rho2 = b12 * b12 + b22 * b22 + b32 * b32;
        float rho3 = b13 * b13 + b23 * b23 + b33 * b33;
        bool c;
        c = rho1 < rho2;
        condNegSwap(c, b11, b12); condNegSwap(c, v11, v12);
        condNegSwap(c, b21, b22); condNegSwap(c, v21, v22);
        condNegSwap(c, b31, b32); condNegSwap(c, v31, v32);
        condSwap(c, rho1, rho2);
        c = rho1 < rho3;
        condNegSwap(c, b11, b13); condNegSwap(c, v11, v13);
        condNegSwap(c, b21, b23); condNegSwap(c, v21, v23);
        condNegSwap(c, b31, b33); condNegSwap(c, v31, v33);
        condSwap(c, rho1, rho3);
        c = rho2 < rho3;
        condNegSwap(c, b12, b13); condNegSwap(c, v12, v13);
        condNegSwap(c, b22, b23); condNegSwap(c, v22, v23);
        condNegSwap(c, b32, b33); condNegSwap(c, v32, v33);

        // ---- QR decomposition of B via 3 Givens rotations ----
        float ch1, sh1, ch2, sh2, ch3, sh3, aa, bb;
        // zero b21
        qrGivens(b11, b21, ch1, sh1);
        aa = 1.0f - 2.0f * sh1 * sh1;
        bb = 2.0f * ch1 * sh1;
        float r11 =  aa * b11 + bb * b21, r12 =  aa * b12 + bb * b22, r13 =  aa * b13 + bb * b23;
        float r21 = -bb * b11 + aa * b21, r22 = -bb * b12 + aa * b22, r23 = -bb * b13 + aa * b23;
        float r31 = b31, r32 = b32, r33 = b33;
        // zero r31
        qrGivens(r11, r31, ch2, sh2);
        aa = 1.0f - 2.0f * sh2 * sh2;
        bb = 2.0f * ch2 * sh2;
        b11 =  aa * r11 + bb * r31; b12 =  aa * r12 + bb * r32; b13 =  aa * r13 + bb * r33;
        b21 = r21;                  b22 = r22;                  b23 = r23;
        b31 = -bb * r11 + aa * r31; b32 = -bb * r12 + aa * r32; b33 = -bb * r13 + aa * r33;
        // zero b32
        qrGivens(b22, b32, ch3, sh3);
        aa = 1.0f - 2.0f * sh3 * sh3;
        bb = 2.0f * ch3 * sh3;
        r11 = b11;                  r12 = b12;                  r13 = b13;
        r22 =  aa * b22 + bb * b32;
        r33 = -bb * b23 + aa * b33;

        // cumulative Q = Q1 * Q2 * Q3 (closed form)
        float sh12 = sh1 * sh1, sh22 = sh2 * sh2, sh32 = sh3 * sh3;
        float u11 = (-1.0f + 2.0f * sh12) * (-1.0f + 2.0f * sh22);
        float u12 = 4.0f * ch2 * ch3 * (-1.0f + 2.0f * sh12) * sh2 * sh3
                  + 2.0f * ch1 * sh1 * (-1.0f + 2.0f * sh32);
        float u13 = 4.0f * ch1 * ch3 * sh1 * sh3
                  - 2.0f * ch2 * (-1.0f + 2.0f * sh12) * sh2 * (-1.0f + 2.0f * sh32);
        float u21 = 2.0f * ch1 * sh1 * (1.0f - 2.0f * sh22);
        float u22 = -8.0f * ch1 * ch2 * ch3 * sh1 * sh2 * sh3
                  + (-1.0f + 2.0f * sh12) * (-1.0f + 2.0f * sh32);
        float u23 = -2.0f * ch3 * sh3
                  + 4.0f * sh1 * (ch3 * sh1 * sh3 + ch1 * ch2 * sh2 * (-1.0f + 2.0f * sh32));
        float u31 = 2.0f * ch2 * sh2;
        float u32 = 2.0f * ch3 * (1.0f - 2.0f * sh22) * sh3;
        float u33 = (-1.0f + 2.0f * sh22) * (-1.0f + 2.0f * sh32);

        // ---- non-negative sigmas; fold signs into reconstruction factors ----
        float sg1 = r11 < 0.0f ? -1.0f : 1.0f;
        float sg2 = r22 < 0.0f ? -1.0f : 1.0f;
        float sg3 = r33 < 0.0f ? -1.0f : 1.0f;
        float sig1 = fabsf(r11), sig2 = fabsf(r22), sig3 = fabsf(r33);

        // ---- Drucker-Prager return mapping ----
        float ylog = __ldg(ylog_p);
        float nu   = __ldg(nu_p);
        float phi  = __ldg(phi_p);
        float coh  = __ldg(coh_p);
        float E = __expf(ylog);
        float sinphi = __sinf(phi * DEG2RAD);
        float alpha = sqrtf(2.0f / 3.0f) * 2.0f * sinphi / (3.0f - sinphi);
        float mu = E / (2.0f * (1.0f + nu));
        float la = E * nu / ((1.0f + nu) * (1.0f - 2.0f * nu));
        float coef = (3.0f * la + 2.0f * mu) / (2.0f * mu) * alpha;

        float e1 = __logf(fmaxf(sig1, SIGMA_MIN));
        float e2 = __logf(fmaxf(sig2, SIGMA_MIN));
        float e3 = __logf(fmaxf(sig3, SIGMA_MIN));
        float tr = e1 + e2 + e3;
        float m = tr * (1.0f / 3.0f);
        float h1 = e1 - m, h2 = e2 - m, h3 = e3 - m;
        float nrm = fmaxf(sqrtf(h1 * h1 + h2 * h2 + h3 * h3), NORM_EPS);
        float st = tr - coh * 3.0f;
        float dg = nrm + coef * st;
        float k = fmaxf(dg, 0.0f) / nrm;
        bool yield = st < 0.0f;
        float c1 = yield ? (e1 - k * h1) : coh;
        float c2 = yield ? (e2 - k * h2) : coh;
        float c3 = yield ? (e3 - k * h3) : coh;
        float t1 = __expf(c1) * sg1;
        float t2 = __expf(c2) * sg2;
        float t3 = __expf(c3) * sg3;

        // ---- F_corrected = U * diag(t) * V^T ----
        float p11 = u11 * t1, p12 = u12 * t2, p13 = u13 * t3;
        float p21 = u21 * t1, p22 = u22 * t2, p23 = u23 * t3;
        float p31 = u31 * t1, p32 = u32 * t2, p33 = u33 * t3;

        float* o = sm + tid * 9;
        o[0] = p11 * v11 + p12 * v12 + p13 * v13;
        o[1] = p11 * v21 + p12 * v22 + p13 * v23;
        o[2] = p11 * v31 + p12 * v32 + p13 * v33;
        o[3] = p21 * v11 + p22 * v12 + p23 * v13;
        o[4] = p21 * v21 + p22 * v22 + p23 * v23;
        o[5] = p21 * v31 + p22 * v32 + p23 * v33;
        o[6] = p31 * v11 + p32 * v12 + p33 * v13;
        o[7] = p31 * v21 + p32 * v22 + p33 * v23;
        o[8] = p31 * v31 + p32 * v32 + p33 * v33;
    }
    __syncthreads();

    // ---- coalesced store: smem -> global ----
    if (cnt == BLOCK) {
        float4* gv = (float4*)(out + (size_t)base * 9);
        const float4* sv = (const float4*)sm;
        #pragma unroll
        for (int k = tid; k < BLOCK * 9 / 4; k += BLOCK) gv[k] = sv[k];
    } else {
        float* g = out + (size_t)base * 9;
        for (int k = tid; k < nflt; k += BLOCK) g[k] = sm[k];
    }
}

extern "C" void kernel_launch(void* const* d_in, const int* in_sizes, int n_in,
                              void* d_out, int out_size) {
    const float* F    = (const float*)d_in[0];
    const float* ylog = (const float*)d_in[1];
    const float* nu   = (const float*)d_in[2];
    const float* phi  = (const float*)d_in[3];
    const float* coh  = (const float*)d_in[4];
    float* out = (float*)d_out;
    int n = in_sizes[0] / 9;
    int grid = (n + BLOCK - 1) / BLOCK;
    dp_plasticity_kernel<<<grid, BLOCK>>>(F, ylog, nu, phi, coh, out, n);
}

// round 2
// speedup vs baseline: 1.1573x; 1.1573x over previous
#include <cuda_runtime.h>
#include <cuda_bf16.h>
#include <math.h>

#define GAMMA_J 5.828427124746190f   // 3 + 2*sqrt(2)
#define CSTAR   0.923879532511287f   // cos(pi/8)
#define SSTAR   0.3826834323650897f  // sin(pi/8)
#define DEG2RAD 0.017453292519943295f
#define SIGMA_MIN 0.05f
#define NORM_EPS 1e-10f

#define BLOCK 256

// Approximate Givens quaternion (McAdams et al.)
__device__ __forceinline__ void approxGivens(float a11, float a12, float a22,
                                             float &ch, float &sh) {
    ch = 2.0f * (a11 - a22);
    sh = a12;
    bool b = GAMMA_J * sh * sh < ch * ch;
    float w = rsqrtf(ch * ch + sh * sh);
    ch = b ? w * ch : CSTAR;
    sh = b ? w * sh : SSTAR;
}

// One Jacobi conjugation step with cyclic permutation. x,y,z are literal
// constants at every call site -> q[] stays in registers.
__device__ __forceinline__ void jacobiConj(const int x, const int y, const int z,
    float &s11, float &s21, float &s22, float &s31, float &s32, float &s33,
    float *q) {
    float ch, sh;
    approxGivens(s11, s21, s22, ch, sh);
    float a = ch * ch - sh * sh;
    float b = 2.0f * sh * ch;

    float _s11 = s11, _s21 = s21, _s22 = s22, _s31 = s31, _s32 = s32, _s33 = s33;
    s11 = a * (a * _s11 + b * _s21) + b * (a * _s21 + b * _s22);
    s21 = a * (-b * _s11 + a * _s21) + b * (-b * _s21 + a * _s22);
    s22 = -b * (-b * _s11 + a * _s21) + a * (-b * _s21 + a * _s22);
    s31 = a * _s31 + b * _s32;
    s32 = -b * _s31 + a * _s32;
    s33 = _s33;

    // accumulate rotation into quaternion
    float tmp[3];
    tmp[0] = q[0] * sh;
    tmp[1] = q[1] * sh;
    tmp[2] = q[2] * sh;
    sh *= q[3];
    q[0] *= ch; q[1] *= ch; q[2] *= ch; q[3] *= ch;
    q[z] += sh;
    q[3] -= tmp[z];
    q[x] += tmp[y];
    q[y] -= tmp[x];

    // cyclic re-arrangement for next pivot
    _s11 = s22; _s21 = s32; _s22 = s33;
    _s31 = s21; _s32 = s31; _s33 = s11;
    s11 = _s11; s21 = _s21; s22 = _s22;
    s31 = _s31; s32 = _s32; s33 = _s33;
}

__global__ void __launch_bounds__(BLOCK)
dp_plasticity_kernel(const float* __restrict__ F,
                     const float* __restrict__ ylog_p,
                     const float* __restrict__ nu_p,
                     const float* __restrict__ phi_p,
                     const float* __restrict__ coh_p,
                     float* __restrict__ out, int n) {
    __shared__ float sm[BLOCK * 9];

    const int tid  = threadIdx.x;
    const int base = blockIdx.x * BLOCK;
    const int cnt  = min(BLOCK, n - base);          // matrices in this block
    const int nflt = cnt * 9;

    // ---- coalesced load: global -> smem ----
    if (cnt == BLOCK) {
        const float4* gv = (const float4*)(F + (size_t)base * 9);
        float4* sv = (float4*)sm;
        #pragma unroll
        for (int k = tid; k < BLOCK * 9 / 4; k += BLOCK) sv[k] = gv[k];
    } else {
        const float* g = F + (size_t)base * 9;
        for (int k = tid; k < nflt; k += BLOCK) sm[k] = g[k];
    }
    __syncthreads();

    if (tid < cnt) {
        const float* a = sm + tid * 9;
        float a11 = a[0], a12 = a[1], a13 = a[2];
        float a21 = a[3], a22 = a[4], a23 = a[5];
        float a31 = a[6], a32 = a[7], a33 = a[8];

        // ---- S = A^T A (symmetric) ----
        float s11 = a11 * a11 + a21 * a21 + a31 * a31;
        float s21 = a11 * a12 + a21 * a22 + a31 * a32;
        float s22 = a12 * a12 + a22 * a22 + a32 * a32;
        float s31 = a11 * a13 + a21 * a23 + a31 * a33;
        float s32 = a12 * a13 + a22 * a23 + a32 * a33;
        float s33 = a13 * a13 + a23 * a23 + a33 * a33;

        // ---- Jacobi eigenanalysis (4 sweeps) -> quaternion ----
        float q[4] = {0.0f, 0.0f, 0.0f, 1.0f};
        #pragma unroll
        for (int sweep = 0; sweep < 4; sweep++) {
            jacobiConj(0, 1, 2, s11, s21, s22, s31, s32, s33, q);
            jacobiConj(1, 2, 0, s11, s21, s22, s31, s32, s33, q);
            jacobiConj(2, 0, 1, s11, s21, s22, s31, s32, s33, q);
        }

        // ---- quaternion -> V (normalize first) ----
        float qs = rsqrtf(q[0] * q[0] + q[1] * q[1] + q[2] * q[2] + q[3] * q[3]);
        float qx = q[0] * qs, qy = q[1] * qs, qz = q[2] * qs, qw = q[3] * qs;
        float v11 = 1.0f - 2.0f * (qy * qy + qz * qz);
        float v12 = 2.0f * (qx * qy - qw * qz);
        float v13 = 2.0f * (qx * qz + qw * qy);
        float v21 = 2.0f * (qx * qy + qw * qz);
        float v22 = 1.0f - 2.0f * (qx * qx + qz * qz);
        float v23 = 2.0f * (qy * qz - qw * qx);
        float v31 = 2.0f * (qx * qz - qw * qy);
        float v32 = 2.0f * (qy * qz + qw * qx);
        float v33 = 1.0f - 2.0f * (qx * qx + qy * qy);

        // ---- B = A * V ; columns b_j = sigma_j * u_j ----
        float b11 = a11 * v11 + a12 * v21 + a13 * v31;
        float b12 = a11 * v12 + a12 * v22 + a13 * v32;
        float b13 = a11 * v13 + a12 * v23 + a13 * v33;
        float b21 = a21 * v11 + a22 * v21 + a23 * v31;
        float b22 = a21 * v12 + a22 * v22 + a23 * v32;
        float b23 = a21 * v13 + a22 * v23 + a23 * v33;
        float b31 = a31 * v11 + a32 * v21 + a33 * v31;
        float b32 = a31 * v12 + a32 * v22 + a33 * v32;
        float b33 = a31 * v13 + a32 * v23 + a33 * v33;

        // ---- sigmas directly from column norms (no sort, no QR needed:
        //      B's columns are orthogonal, return map is permutation-
        //      equivariant, and sign/degeneracy freedom cancels in the
        //      final product) ----
        float rho1 = b11 * b11 + b21 * b21 + b31 * b31;
        float rho2 = b12 * b12 + b22 * b22 + b32 * b32;
        float rho3 = b13 * b13 + b23 * b23 + b33 * b33;
        float i1 = rsqrtf(fmaxf(rho1, 1e-30f));
        float i2 = rsqrtf(fmaxf(rho2, 1e-30f));
        float i3 = rsqrtf(fmaxf(rho3, 1e-30f));
        float sig1 = rho1 * i1;   // sqrt(rho)
        float sig2 = rho2 * i2;
        float sig3 = rho3 * i3;

        // ---- Drucker-Prager return mapping ----
        float ylog = __ldg(ylog_p);
        float nu   = __ldg(nu_p);
        float phi  = __ldg(phi_p);
        float coh  = __ldg(coh_p);
        float E = __expf(ylog);
        float sinphi = __sinf(phi * DEG2RAD);
        float alpha = sqrtf(2.0f / 3.0f) * 2.0f * sinphi / (3.0f - sinphi);
        float mu = E / (2.0f * (1.0f + nu));
        float la = E * nu / ((1.0f + nu) * (1.0f - 2.0f * nu));
        float coef = (3.0f * la + 2.0f * mu) / (2.0f * mu) * alpha;

        float e1 = __logf(fmaxf(sig1, SIGMA_MIN));
        float e2 = __logf(fmaxf(sig2, SIGMA_MIN));
        float e3 = __logf(fmaxf(sig3, SIGMA_MIN));
        float tr = e1 + e2 + e3;
        float m = tr * (1.0f / 3.0f);
        float h1 = e1 - m, h2 = e2 - m, h3 = e3 - m;
        float nrm = fmaxf(sqrtf(h1 * h1 + h2 * h2 + h3 * h3), NORM_EPS);
        float st = tr - coh * 3.0f;
        float dg = nrm + coef * st;
        float k = fmaxf(dg, 0.0f) / nrm;
        bool yield = st < 0.0f;
        float c1 = yield ? (e1 - k * h1) : coh;
        float c2 = yield ? (e2 - k * h2) : coh;
        float c3 = yield ? (e3 - k * h3) : coh;

        // w_j = exp(c_j) / sigma_j  (U never materialized: u_j = b_j/sigma_j)
        float w1 = __expf(c1) * i1;
        float w2 = __expf(c2) * i2;
        float w3 = __expf(c3) * i3;

        // ---- F_corrected = sum_j w_j * b_j * v_j^T ----
        float p11 = b11 * w1, p12 = b12 * w2, p13 = b13 * w3;
        float p21 = b21 * w1, p22 = b22 * w2, p23 = b23 * w3;
        float p31 = b31 * w1, p32 = b32 * w2, p33 = b33 * w3;

        float* o = sm + tid * 9;
        o[0] = p11 * v11 + p12 * v12 + p13 * v13;
        o[1] = p11 * v21 + p12 * v22 + p13 * v23;
        o[2] = p11 * v31 + p12 * v32 + p13 * v33;
        o[3] = p21 * v11 + p22 * v12 + p23 * v13;
        o[4] = p21 * v21 + p22 * v22 + p23 * v23;
        o[5] = p21 * v31 + p22 * v32 + p23 * v33;
        o[6] = p31 * v11 + p32 * v12 + p33 * v13;
        o[7] = p31 * v21 + p32 * v22 + p33 * v23;
        o[8] = p31 * v31 + p32 * v32 + p33 * v33;
    }
    __syncthreads();

    // ---- coalesced store: smem -> global ----
    if (cnt == BLOCK) {
        float4* gv = (float4*)(out + (size_t)base * 9);
        const float4* sv = (const float4*)sm;
        #pragma unroll
        for (int k = tid; k < BLOCK * 9 / 4; k += BLOCK) gv[k] = sv[k];
    } else {
        float* g = out + (size_t)base * 9;
        for (int k = tid; k < nflt; k += BLOCK) g[k] = sm[k];
    }
}

extern "C" void kernel_launch(void* const* d_in, const int* in_sizes, int n_in,
                              void* d_out, int out_size) {
    const float* F    = (const float*)d_in[0];
    const float* ylog = (const float*)d_in[1];
    const float* nu   = (const float*)d_in[2];
    const float* phi  = (const float*)d_in[3];
    const float* coh  = (const float*)d_in[4];
    float* out = (float*)d_out;
    int n = in_sizes[0] / 9;
    int grid = (n + BLOCK - 1) / BLOCK;
    dp_plasticity_kernel<<<grid, BLOCK>>>(F, ylog, nu, phi, coh, out, n);
}

// round 3
// speedup vs baseline: 1.3487x; 1.1654x over previous
#include <cuda_runtime.h>
#include <cuda_bf16.h>
#include <math.h>

#define GAMMA_J 5.828427124746190f   // 3 + 2*sqrt(2)
#define CSTAR   0.923879532511287f   // cos(pi/8)
#define SSTAR   0.3826834323650897f  // sin(pi/8)
#define DEG2RAD 0.017453292519943295f
#define SIGMA_MIN 0.05f

#define BLOCK 128
#define MPB   (2 * BLOCK)   // matrices per block

typedef unsigned long long u64;
struct f2 { u64 v; };

__device__ __forceinline__ f2 mk2(float lo, float hi) {
    f2 r; asm("mov.b64 %0, {%1, %2};" : "=l"(r.v) : "f"(lo), "f"(hi)); return r;
}
__device__ __forceinline__ f2 bc2(float x) { return mk2(x, x); }
__device__ __forceinline__ void un2(f2 a, float &lo, float &hi) {
    asm("mov.b64 {%0, %1}, %2;" : "=f"(lo), "=f"(hi) : "l"(a.v));
}
__device__ __forceinline__ f2 add2(f2 a, f2 b) {
    f2 r; asm("add.rn.f32x2 %0, %1, %2;" : "=l"(r.v) : "l"(a.v), "l"(b.v)); return r;
}
__device__ __forceinline__ f2 mul2(f2 a, f2 b) {
    f2 r; asm("mul.rn.f32x2 %0, %1, %2;" : "=l"(r.v) : "l"(a.v), "l"(b.v)); return r;
}
__device__ __forceinline__ f2 fma2(f2 a, f2 b, f2 c) {
    f2 r; asm("fma.rn.f32x2 %0, %1, %2, %3;" : "=l"(r.v) : "l"(a.v), "l"(b.v), "l"(c.v)); return r;
}
__device__ __forceinline__ f2 neg2(f2 a) {
    f2 r; u64 m = 0x8000000080000000ULL;
    asm("xor.b64 %0, %1, %2;" : "=l"(r.v) : "l"(a.v), "l"(m)); return r;
}

// One packed Jacobi conjugation step with cyclic permutation.
__device__ __forceinline__ void jstep(const int x, const int y, const int z,
    f2 &s11, f2 &s21, f2 &s22, f2 &s31, f2 &s32, f2 &s33, f2 *q)
{
    const f2 M2  = bc2(-2.0f);
    const f2 ONE = bc2(1.0f);

    // approximate Givens quaternion (per-half select, packed arithmetic)
    f2 chr = fma2(s22, M2, add2(s11, s11));    // 2*(s11 - s22)
    f2 shr = s21;
    f2 ch2 = mul2(chr, chr);
    f2 sh2 = mul2(shr, shr);
    f2 sum = add2(ch2, sh2);
    float suml, sumh; un2(sum, suml, sumh);
    f2 w = mk2(rsqrtf(suml), rsqrtf(sumh));
    f2 wch = mul2(w, chr);
    f2 wsh = mul2(w, shr);
    float c2l, c2h, s2l, s2h; un2(ch2, c2l, c2h); un2(sh2, s2l, s2h);
    float wchl, wchh, wshl, wshh; un2(wch, wchl, wchh); un2(wsh, wshl, wshh);
    bool bl = GAMMA_J * s2l < c2l;
    bool bh = GAMMA_J * s2h < c2h;
    f2 ch = mk2(bl ? wchl : CSTAR, bh ? wchh : CSTAR);
    f2 sh = mk2(bl ? wshl : SSTAR, bh ? wshh : SSTAR);

    // (ch,sh) is unit: a = ch^2 - sh^2 = 1 - 2 sh^2
    f2 sh2s = mul2(sh, sh);
    f2 aa = fma2(sh2s, M2, ONE);
    f2 bb = mul2(add2(sh, sh), ch);
    f2 nb = neg2(bb);

    // S' = G^T S G
    f2 t1 = fma2(aa, s11, mul2(bb, s21));
    f2 t2 = fma2(aa, s21, mul2(bb, s22));
    f2 u1 = fma2(nb, s11, mul2(aa, s21));
    f2 u2 = fma2(nb, s21, mul2(aa, s22));
    f2 ns11 = fma2(aa, t1, mul2(bb, t2));
    f2 ns21 = fma2(aa, u1, mul2(bb, u2));
    f2 ns22 = fma2(nb, u1, mul2(aa, u2));
    f2 ns31 = fma2(aa, s31, mul2(bb, s32));
    f2 ns32 = fma2(nb, s31, mul2(aa, s32));
    f2 ns33 = s33;

    // quaternion accumulate (fused: q *= ch, then cross terms)
    f2 nsh = neg2(sh);
    f2 qx = q[x], qy = q[y], qz = q[z], qw = q[3];
    q[x] = fma2(qx, ch, mul2(qy, sh));
    q[y] = fma2(qy, ch, mul2(qx, nsh));
    q[z] = fma2(qz, ch, mul2(qw, sh));
    q[3] = fma2(qw, ch, mul2(qz, nsh));

    // cyclic re-arrangement for next pivot
    s11 = ns22; s21 = ns32; s22 = ns33;
    s31 = ns21; s32 = ns31; s33 = ns11;
}

__global__ void __launch_bounds__(BLOCK)
dp_plasticity_kernel(const float* __restrict__ F,
                     const float* __restrict__ ylog_p,
                     const float* __restrict__ nu_p,
                     const float* __restrict__ phi_p,
                     const float* __restrict__ coh_p,
                     float* __restrict__ out, int n) {
    __shared__ float sm[MPB * 9];

    const int tid  = threadIdx.x;
    const int base = blockIdx.x * MPB;
    const int cnt  = min(MPB, n - base);
    const int nflt = cnt * 9;

    // ---- coalesced load: global -> smem (linear layout) ----
    if (cnt == MPB) {
        const float4* gv = (const float4*)(F + (size_t)base * 9);
        float4* sv = (float4*)sm;
        #pragma unroll
        for (int k = tid; k < MPB * 9 / 4; k += BLOCK) sv[k] = gv[k];
    } else {
        const float* g = F + (size_t)base * 9;
        for (int k = tid; k < nflt; k += BLOCK) sm[k] = g[k];
    }
    __syncthreads();

    {
        // matrices (tid) and (tid + BLOCK): lane stride 9 words -> conflict-free
        const float* A0 = sm + tid * 9;
        const float* A1 = sm + (tid + BLOCK) * 9;
        f2 a11 = mk2(A0[0], A1[0]);
        f2 a12 = mk2(A0[1], A1[1]);
        f2 a13 = mk2(A0[2], A1[2]);
        f2 a21 = mk2(A0[3], A1[3]);
        f2 a22 = mk2(A0[4], A1[4]);
        f2 a23 = mk2(A0[5], A1[5]);
        f2 a31 = mk2(A0[6], A1[6]);
        f2 a32 = mk2(A0[7], A1[7]);
        f2 a33 = mk2(A0[8], A1[8]);

        // ---- S = A^T A ----
        f2 s11 = fma2(a11, a11, fma2(a21, a21, mul2(a31, a31)));
        f2 s21 = fma2(a11, a12, fma2(a21, a22, mul2(a31, a32)));
        f2 s22 = fma2(a12, a12, fma2(a22, a22, mul2(a32, a32)));
        f2 s31 = fma2(a11, a13, fma2(a21, a23, mul2(a31, a33)));
        f2 s32 = fma2(a12, a13, fma2(a22, a23, mul2(a32, a33)));
        f2 s33 = fma2(a13, a13, fma2(a23, a23, mul2(a33, a33)));

        // ---- Jacobi (4 sweeps) -> quaternion ----
        f2 q[4] = { bc2(0.0f), bc2(0.0f), bc2(0.0f), bc2(1.0f) };
        #pragma unroll
        for (int sweep = 0; sweep < 4; sweep++) {
            jstep(0, 1, 2, s11, s21, s22, s31, s32, s33, q);
            jstep(1, 2, 0, s11, s21, s22, s31, s32, s33, q);
            jstep(2, 0, 1, s11, s21, s22, s31, s32, s33, q);
        }

        // ---- quaternion -> V ----
        f2 qn = fma2(q[0], q[0], fma2(q[1], q[1], fma2(q[2], q[2], mul2(q[3], q[3]))));
        float qnl, qnh; un2(qn, qnl, qnh);
        f2 qs = mk2(rsqrtf(qnl), rsqrtf(qnh));
        f2 qx = mul2(q[0], qs), qy = mul2(q[1], qs), qz = mul2(q[2], qs), qw = mul2(q[3], qs);

        const f2 ONE = bc2(1.0f);
        const f2 M2  = bc2(-2.0f);
        const f2 P2  = bc2(2.0f);
        f2 xx = mul2(qx, qx), yy = mul2(qy, qy), zz = mul2(qz, qz);
        f2 xy = mul2(qx, qy), xz = mul2(qx, qz), yz = mul2(qy, qz);
        f2 wx = mul2(qw, qx), wy = mul2(qw, qy), wz = mul2(qw, qz);

        f2 v11 = fma2(add2(yy, zz), M2, ONE);
        f2 v22 = fma2(add2(xx, zz), M2, ONE);
        f2 v33 = fma2(add2(xx, yy), M2, ONE);
        f2 nwz = neg2(wz), nwx = neg2(wx), nwy = neg2(wy);
        f2 v12 = mul2(P2, add2(xy, nwz));
        f2 v21 = mul2(P2, add2(xy, wz));
        f2 v13 = mul2(P2, add2(xz, wy));
        f2 v31 = mul2(P2, add2(xz, nwy));
        f2 v23 = mul2(P2, add2(yz, nwx));
        f2 v32 = mul2(P2, add2(yz, wx));

        // ---- B = A * V ; columns b_j = sigma_j * u_j ----
        f2 b11 = fma2(a11, v11, fma2(a12, v21, mul2(a13, v31)));
        f2 b12 = fma2(a11, v12, fma2(a12, v22, mul2(a13, v32)));
        f2 b13 = fma2(a11, v13, fma2(a12, v23, mul2(a13, v33)));
        f2 b21 = fma2(a21, v11, fma2(a22, v21, mul2(a23, v31)));
        f2 b22 = fma2(a21, v12, fma2(a22, v22, mul2(a23, v32)));
        f2 b23 = fma2(a21, v13, fma2(a22, v23, mul2(a23, v33)));
        f2 b31 = fma2(a31, v11, fma2(a32, v21, mul2(a33, v31)));
        f2 b32 = fma2(a31, v12, fma2(a32, v22, mul2(a33, v32)));
        f2 b33 = fma2(a31, v13, fma2(a32, v23, mul2(a33, v33)));

        // ---- sigma_j = ||b_j||  (nonnegative; no sort/QR needed) ----
        f2 rho1 = fma2(b11, b11, fma2(b21, b21, mul2(b31, b31)));
        f2 rho2 = fma2(b12, b12, fma2(b22, b22, mul2(b32, b32)));
        f2 rho3 = fma2(b13, b13, fma2(b23, b23, mul2(b33, b33)));

        // ---- material params (uniform scalars) ----
        float ylog = __ldg(ylog_p);
        float nu   = __ldg(nu_p);
        float phi  = __ldg(phi_p);
        float coh  = __ldg(coh_p);
        float E = __expf(ylog);
        float sinphi = __sinf(phi * DEG2RAD);
        float alpha = sqrtf(2.0f / 3.0f) * 2.0f * sinphi / (3.0f - sinphi);
        float mu = E / (2.0f * (1.0f + nu));
        float la = E * nu / ((1.0f + nu) * (1.0f - 2.0f * nu));
        float coef = (3.0f * la + 2.0f * mu) / (2.0f * mu) * alpha;

        // ---- per-half sigma -> log strain (MUFU-heavy: scalar halves) ----
        float r1l, r1h, r2l, r2h, r3l, r3h;
        un2(rho1, r1l, r1h); un2(rho2, r2l, r2h); un2(rho3, r3l, r3h);
        float i1l = rsqrtf(fmaxf(r1l, 1e-30f)), i1h = rsqrtf(fmaxf(r1h, 1e-30f));
        float i2l = rsqrtf(fmaxf(r2l, 1e-30f)), i2h = rsqrtf(fmaxf(r2h, 1e-30f));
        float i3l = rsqrtf(fmaxf(r3l, 1e-30f)), i3h = rsqrtf(fmaxf(r3h, 1e-30f));
        float e1l = __logf(fmaxf(r1l * i1l, SIGMA_MIN)), e1h = __logf(fmaxf(r1h * i1h, SIGMA_MIN));
        float e2l = __logf(fmaxf(r2l * i2l, SIGMA_MIN)), e2h = __logf(fmaxf(r2h * i2h, SIGMA_MIN));
        float e3l = __logf(fmaxf(r3l * i3l, SIGMA_MIN)), e3h = __logf(fmaxf(r3h * i3h, SIGMA_MIN));

        f2 e1 = mk2(e1l, e1h), e2 = mk2(e2l, e2h), e3 = mk2(e3l, e3h);
        f2 tr = add2(e1, add2(e2, e3));
        f2 nm = mul2(tr, bc2(-1.0f / 3.0f));
        f2 h1 = add2(e1, nm), h2 = add2(e2, nm), h3 = add2(e3, nm);
        f2 nrm2 = fma2(h1, h1, fma2(h2, h2, mul2(h3, h3)));

        float n2l, n2h; un2(nrm2, n2l, n2h);
        n2l = fmaxf(n2l, 1e-20f); n2h = fmaxf(n2h, 1e-20f);
        float rnl = rsqrtf(n2l), rnh = rsqrtf(n2h);
        float nrml = n2l * rnl, nrmh = n2h * rnh;   // max(||eps_hat||, 1e-10)

        f2 st = add2(tr, bc2(-3.0f * coh));
        float stl, sth; un2(st, stl, sth);
        float kl = fmaxf(nrml + coef * stl, 0.0f) * rnl;
        float kh = fmaxf(nrmh + coef * sth, 0.0f) * rnh;
        f2 nk = mk2(-kl, -kh);
        f2 ce1 = fma2(nk, h1, e1);
        f2 ce2 = fma2(nk, h2, e2);
        f2 ce3 = fma2(nk, h3, e3);

        float c1l, c1h, c2lo, c2hi, c3l, c3h;
        un2(ce1, c1l, c1h); un2(ce2, c2lo, c2hi); un2(ce3, c3l, c3h);
        bool yl = stl < 0.0f, yh = sth < 0.0f;
        // w_j = exp(eps_corr_j) / sigma_j   (U never materialized)
        f2 w1 = mk2(__expf(yl ? c1l : coh) * i1l, __expf(yh ? c1h : coh) * i1h);
        f2 w2 = mk2(__expf(yl ? c2lo : coh) * i2l, __expf(yh ? c2hi : coh) * i2h);
        f2 w3 = mk2(__expf(yl ? c3l : coh) * i3l, __expf(yh ? c3h : coh) * i3h);

        // ---- F_corrected = sum_j w_j * b_j * v_j^T ----
        f2 p11 = mul2(b11, w1), p12 = mul2(b12, w2), p13 = mul2(b13, w3);
        f2 p21 = mul2(b21, w1), p22 = mul2(b22, w2), p23 = mul2(b23, w3);
        f2 p31 = mul2(b31, w1), p32 = mul2(b32, w2), p33 = mul2(b33, w3);

        f2 o0 = fma2(p11, v11, fma2(p12, v12, mul2(p13, v13)));
        f2 o1 = fma2(p11, v21, fma2(p12, v22, mul2(p13, v23)));
        f2 o2 = fma2(p11, v31, fma2(p12, v32, mul2(p13, v33)));
        f2 o3 = fma2(p21, v11, fma2(p22, v12, mul2(p23, v13)));
        f2 o4 = fma2(p21, v21, fma2(p22, v22, mul2(p23, v23)));
        f2 o5 = fma2(p21, v31, fma2(p22, v32, mul2(p23, v33)));
        f2 o6 = fma2(p31, v11, fma2(p32, v12, mul2(p33, v13)));
        f2 o7 = fma2(p31, v21, fma2(p32, v22, mul2(p33, v23)));
        f2 o8 = fma2(p31, v31, fma2(p32, v32, mul2(p33, v33)));

        __syncthreads();   // staging buffer reuse
        float* O0 = sm + tid * 9;
        float* O1 = sm + (tid + BLOCK) * 9;
        float lo, hi;
        un2(o0, lo, hi); O0[0] = lo; O1[0] = hi;
        un2(o1, lo, hi); O0[1] = lo; O1[1] = hi;
        un2(o2, lo, hi); O0[2] = lo; O1[2] = hi;
        un2(o3, lo, hi); O0[3] = lo; O1[3] = hi;
        un2(o4, lo, hi); O0[4] = lo; O1[4] = hi;
        un2(o5, lo, hi); O0[5] = lo; O1[5] = hi;
        un2(o6, lo, hi); O0[6] = lo; O1[6] = hi;
        un2(o7, lo, hi); O0[7] = lo; O1[7] = hi;
        un2(o8, lo, hi); O0[8] = lo; O1[8] = hi;
    }
    __syncthreads();

    // ---- coalesced store: smem -> global ----
    if (cnt == MPB) {
        float4* gv = (float4*)(out + (size_t)base * 9);
        const float4* sv = (const float4*)sm;
        #pragma unroll
        for (int k = tid; k < MPB * 9 / 4; k += BLOCK) gv[k] = sv[k];
    } else {
        float* g = out + (size_t)base * 9;
        for (int k = tid; k < nflt; k += BLOCK) g[k] = sm[k];
    }
}

extern "C" void kernel_launch(void* const* d_in, const int* in_sizes, int n_in,
                              void* d_out, int out_size) {
    const float* F    = (const float*)d_in[0];
    const float* ylog = (const float*)d_in[1];
    const float* nu   = (const float*)d_in[2];
    const float* phi  = (const float*)d_in[3];
    const float* coh  = (const float*)d_in[4];
    float* out = (float*)d_out;
    int n = in_sizes[0] / 9;
    int grid = (n + MPB - 1) / MPB;
    dp_plasticity_kernel<<<grid, BLOCK>>>(F, ylog, nu, phi, coh, out, n);
}

// round 5
// speedup vs baseline: 1.3563x; 1.0057x over previous
#include <cuda_runtime.h>
#include <cuda_bf16.h>
#include <math.h>

#define GAMMA_J 5.828427124746190f   // 3 + 2*sqrt(2)
#define CSTAR   0.923879532511287f   // cos(pi/8)
#define SSTAR   0.3826834323650897f  // sin(pi/8)
#define DEG2RAD 0.017453292519943295f
#define SIGMA_MIN 0.05f

#define BLOCK 128
#define CHAINS 2
#define MPB   (2 * CHAINS * BLOCK)   // 512 matrices per block

typedef unsigned long long u64;
struct f2 { u64 v; };

__device__ __forceinline__ f2 mk2(float lo, float hi) {
    f2 r; asm("mov.b64 %0, {%1, %2};" : "=l"(r.v) : "f"(lo), "f"(hi)); return r;
}
__device__ __forceinline__ f2 bc2(float x) { return mk2(x, x); }
__device__ __forceinline__ void un2(f2 a, float &lo, float &hi) {
    asm("mov.b64 {%0, %1}, %2;" : "=f"(lo), "=f"(hi) : "l"(a.v));
}
__device__ __forceinline__ f2 add2(f2 a, f2 b) {
    f2 r; asm("add.rn.f32x2 %0, %1, %2;" : "=l"(r.v) : "l"(a.v), "l"(b.v)); return r;
}
__device__ __forceinline__ f2 mul2(f2 a, f2 b) {
    f2 r; asm("mul.rn.f32x2 %0, %1, %2;" : "=l"(r.v) : "l"(a.v), "l"(b.v)); return r;
}
__device__ __forceinline__ f2 fma2(f2 a, f2 b, f2 c) {
    f2 r; asm("fma.rn.f32x2 %0, %1, %2, %3;" : "=l"(r.v) : "l"(a.v), "l"(b.v), "l"(c.v)); return r;
}
__device__ __forceinline__ f2 neg2(f2 a) {
    f2 r; u64 m = 0x8000000080000000ULL;
    asm("xor.b64 %0, %1, %2;" : "=l"(r.v) : "l"(a.v), "l"(m)); return r;
}

// One packed Jacobi conjugation step with cyclic permutation.
__device__ __forceinline__ void jstep(const int x, const int y, const int z,
    f2 &s11, f2 &s21, f2 &s22, f2 &s31, f2 &s32, f2 &s33, f2 *q)
{
    const f2 M2  = bc2(-2.0f);
    const f2 ONE = bc2(1.0f);

    f2 chr = fma2(s22, M2, add2(s11, s11));    // 2*(s11 - s22)
    f2 shr = s21;
    f2 ch2 = mul2(chr, chr);
    f2 sh2 = mul2(shr, shr);
    f2 sum = add2(ch2, sh2);
    float suml, sumh; un2(sum, suml, sumh);
    f2 w = mk2(rsqrtf(suml), rsqrtf(sumh));
    f2 wch = mul2(w, chr);
    f2 wsh = mul2(w, shr);
    float c2l, c2h, s2l, s2h; un2(ch2, c2l, c2h); un2(sh2, s2l, s2h);
    float wchl, wchh, wshl, wshh; un2(wch, wchl, wchh); un2(wsh, wshl, wshh);
    bool bl = GAMMA_J * s2l < c2l;
    bool bh = GAMMA_J * s2h < c2h;
    f2 ch = mk2(bl ? wchl : CSTAR, bh ? wchh : CSTAR);
    f2 sh = mk2(bl ? wshl : SSTAR, bh ? wshh : SSTAR);

    // (ch,sh) is unit: a = ch^2 - sh^2 = 1 - 2 sh^2
    f2 sh2s = mul2(sh, sh);
    f2 aa = fma2(sh2s, M2, ONE);
    f2 bb = mul2(add2(sh, sh), ch);
    f2 nb = neg2(bb);

    // S' = G^T S G
    f2 t1 = fma2(aa, s11, mul2(bb, s21));
    f2 t2 = fma2(aa, s21, mul2(bb, s22));
    f2 u1 = fma2(nb, s11, mul2(aa, s21));
    f2 u2 = fma2(nb, s21, mul2(aa, s22));
    f2 ns11 = fma2(aa, t1, mul2(bb, t2));
    f2 ns21 = fma2(aa, u1, mul2(bb, u2));
    f2 ns22 = fma2(nb, u1, mul2(aa, u2));
    f2 ns31 = fma2(aa, s31, mul2(bb, s32));
    f2 ns32 = fma2(nb, s31, mul2(aa, s32));
    f2 ns33 = s33;

    // quaternion accumulate
    f2 nsh = neg2(sh);
    f2 qx = q[x], qy = q[y], qz = q[z], qw = q[3];
    q[x] = fma2(qx, ch, mul2(qy, sh));
    q[y] = fma2(qy, ch, mul2(qx, nsh));
    q[z] = fma2(qz, ch, mul2(qw, sh));
    q[3] = fma2(qw, ch, mul2(qz, nsh));

    // cyclic re-arrangement for next pivot
    s11 = ns22; s21 = ns32; s22 = ns33;
    s31 = ns21; s32 = ns31; s33 = ns11;
}

__global__ void __launch_bounds__(BLOCK)
dp_plasticity_kernel(const float* __restrict__ F,
                     const float* __restrict__ ylog_p,
                     const float* __restrict__ nu_p,
                     const float* __restrict__ phi_p,
                     const float* __restrict__ coh_p,
                     float* __restrict__ out, int n) {
    __shared__ float sm[MPB * 9];

    const int tid  = threadIdx.x;
    const int base = blockIdx.x * MPB;
    const int cnt  = min(MPB, n - base);
    const int nflt = cnt * 9;

    // ---- coalesced load: global -> smem (linear layout) ----
    if (cnt == MPB) {
        const float4* gv = (const float4*)(F + (size_t)base * 9);
        float4* sv = (float4*)sm;
        #pragma unroll
        for (int k = tid; k < MPB * 9 / 4; k += BLOCK) sv[k] = gv[k];
    } else {
        const float* g = F + (size_t)base * 9;
        for (int k = tid; k < nflt; k += BLOCK) sm[k] = g[k];
        // fill the rest so unconditional compute sees finite values
        for (int k = nflt + tid; k < MPB * 9; k += BLOCK) sm[k] = 1.0f;
    }
    __syncthreads();

    // ---- material params (uniform scalars) ----
    float ylog = __ldg(ylog_p);
    float nu   = __ldg(nu_p);
    float phi  = __ldg(phi_p);
    float coh  = __ldg(coh_p);
    float E = __expf(ylog);
    float sinphi = __sinf(phi * DEG2RAD);
    float alpha = sqrtf(2.0f / 3.0f) * 2.0f * sinphi / (3.0f - sinphi);
    float mu = E / (2.0f * (1.0f + nu));
    float la = E * nu / ((1.0f + nu) * (1.0f - 2.0f * nu));
    float coef = (3.0f * la + 2.0f * mu) / (2.0f * mu) * alpha;

    // ================= FRONT: S = A^T A and Jacobi, both chains ============
    f2 s11[CHAINS], s21[CHAINS], s22[CHAINS], s31[CHAINS], s32[CHAINS], s33[CHAINS];
    f2 q[CHAINS][4];

    #pragma unroll
    for (int c = 0; c < CHAINS; c++) {
        const float* A0 = sm + (tid + 2 * c * BLOCK) * 9;
        const float* A1 = sm + (tid + (2 * c + 1) * BLOCK) * 9;
        f2 a11 = mk2(A0[0], A1[0]);
        f2 a12 = mk2(A0[1], A1[1]);
        f2 a13 = mk2(A0[2], A1[2]);
        f2 a21 = mk2(A0[3], A1[3]);
        f2 a22 = mk2(A0[4], A1[4]);
        f2 a23 = mk2(A0[5], A1[5]);
        f2 a31 = mk2(A0[6], A1[6]);
        f2 a32 = mk2(A0[7], A1[7]);
        f2 a33 = mk2(A0[8], A1[8]);
        s11[c] = fma2(a11, a11, fma2(a21, a21, mul2(a31, a31)));
        s21[c] = fma2(a11, a12, fma2(a21, a22, mul2(a31, a32)));
        s22[c] = fma2(a12, a12, fma2(a22, a22, mul2(a32, a32)));
        s31[c] = fma2(a11, a13, fma2(a21, a23, mul2(a31, a33)));
        s32[c] = fma2(a12, a13, fma2(a22, a23, mul2(a32, a33)));
        s33[c] = fma2(a13, a13, fma2(a23, a23, mul2(a33, a33)));
        q[c][0] = bc2(0.0f); q[c][1] = bc2(0.0f);
        q[c][2] = bc2(0.0f); q[c][3] = bc2(1.0f);
    }

    #pragma unroll
    for (int sweep = 0; sweep < 4; sweep++) {
        #pragma unroll
        for (int c = 0; c < CHAINS; c++)
            jstep(0, 1, 2, s11[c], s21[c], s22[c], s31[c], s32[c], s33[c], q[c]);
        #pragma unroll
        for (int c = 0; c < CHAINS; c++)
            jstep(1, 2, 0, s11[c], s21[c], s22[c], s31[c], s32[c], s33[c], q[c]);
        #pragma unroll
        for (int c = 0; c < CHAINS; c++)
            jstep(2, 0, 1, s11[c], s21[c], s22[c], s31[c], s32[c], s33[c], q[c]);
    }

    // ================= BACK: per-chain sequential (register cap) ===========
    #pragma unroll
    for (int c = 0; c < CHAINS; c++) {
        // quaternion -> V
        f2 qn = fma2(q[c][0], q[c][0], fma2(q[c][1], q[c][1],
                 fma2(q[c][2], q[c][2], mul2(q[c][3], q[c][3]))));
        float qnl, qnh; un2(qn, qnl, qnh);
        f2 qs = mk2(rsqrtf(qnl), rsqrtf(qnh));
        f2 qx = mul2(q[c][0], qs), qy = mul2(q[c][1], qs);
        f2 qz = mul2(q[c][2], qs), qw = mul2(q[c][3], qs);

        const f2 ONE = bc2(1.0f);
        const f2 M2  = bc2(-2.0f);
        const f2 P2  = bc2(2.0f);
        f2 xx = mul2(qx, qx), yy = mul2(qy, qy), zz = mul2(qz, qz);
        f2 xy = mul2(qx, qy), xz = mul2(qx, qz), yz = mul2(qy, qz);
        f2 wx = mul2(qw, qx), wy = mul2(qw, qy), wz = mul2(qw, qz);

        f2 v11 = fma2(add2(yy, zz), M2, ONE);
        f2 v22 = fma2(add2(xx, zz), M2, ONE);
        f2 v33 = fma2(add2(xx, yy), M2, ONE);
        f2 nwz = neg2(wz), nwx = neg2(wx), nwy = neg2(wy);
        f2 v12 = mul2(P2, add2(xy, nwz));
        f2 v21 = mul2(P2, add2(xy, wz));
        f2 v13 = mul2(P2, add2(xz, wy));
        f2 v31 = mul2(P2, add2(xz, nwy));
        f2 v23 = mul2(P2, add2(yz, nwx));
        f2 v32 = mul2(P2, add2(yz, wx));

        // reload A from smem (slots untouched so far)
        const float* A0 = sm + (tid + 2 * c * BLOCK) * 9;
        const float* A1 = sm + (tid + (2 * c + 1) * BLOCK) * 9;
        f2 a11 = mk2(A0[0], A1[0]);
        f2 a12 = mk2(A0[1], A1[1]);
        f2 a13 = mk2(A0[2], A1[2]);
        f2 a21 = mk2(A0[3], A1[3]);
        f2 a22 = mk2(A0[4], A1[4]);
        f2 a23 = mk2(A0[5], A1[5]);
        f2 a31 = mk2(A0[6], A1[6]);
        f2 a32 = mk2(A0[7], A1[7]);
        f2 a33 = mk2(A0[8], A1[8]);

        // B = A * V ; columns b_j = sigma_j * u_j
        f2 b11 = fma2(a11, v11, fma2(a12, v21, mul2(a13, v31)));
        f2 b12 = fma2(a11, v12, fma2(a12, v22, mul2(a13, v32)));
        f2 b13 = fma2(a11, v13, fma2(a12, v23, mul2(a13, v33)));
        f2 b21 = fma2(a21, v11, fma2(a22, v21, mul2(a23, v31)));
        f2 b22 = fma2(a21, v12, fma2(a22, v22, mul2(a23, v32)));
        f2 b23 = fma2(a21, v13, fma2(a22, v23, mul2(a23, v33)));
        f2 b31 = fma2(a31, v11, fma2(a32, v21, mul2(a33, v31)));
        f2 b32 = fma2(a31, v12, fma2(a32, v22, mul2(a33, v32)));
        f2 b33 = fma2(a31, v13, fma2(a32, v23, mul2(a33, v33)));

        // sigma_j = ||b_j||
        f2 rho1 = fma2(b11, b11, fma2(b21, b21, mul2(b31, b31)));
        f2 rho2 = fma2(b12, b12, fma2(b22, b22, mul2(b32, b32)));
        f2 rho3 = fma2(b13, b13, fma2(b23, b23, mul2(b33, b33)));

        float r1l, r1h, r2l, r2h, r3l, r3h;
        un2(rho1, r1l, r1h); un2(rho2, r2l, r2h); un2(rho3, r3l, r3h);
        float i1l = rsqrtf(fmaxf(r1l, 1e-30f)), i1h = rsqrtf(fmaxf(r1h, 1e-30f));
        float i2l = rsqrtf(fmaxf(r2l, 1e-30f)), i2h = rsqrtf(fmaxf(r2h, 1e-30f));
        float i3l = rsqrtf(fmaxf(r3l, 1e-30f)), i3h = rsqrtf(fmaxf(r3h, 1e-30f));
        float e1l = __logf(fmaxf(r1l * i1l, SIGMA_MIN)), e1h = __logf(fmaxf(r1h * i1h, SIGMA_MIN));
        float e2l = __logf(fmaxf(r2l * i2l, SIGMA_MIN)), e2h = __logf(fmaxf(r2h * i2h, SIGMA_MIN));
        float e3l = __logf(fmaxf(r3l * i3l, SIGMA_MIN)), e3h = __logf(fmaxf(r3h * i3h, SIGMA_MIN));

        f2 e1 = mk2(e1l, e1h), e2 = mk2(e2l, e2h), e3 = mk2(e3l, e3h);
        f2 tr = add2(e1, add2(e2, e3));
        f2 nm = mul2(tr, bc2(-1.0f / 3.0f));
        f2 h1 = add2(e1, nm), h2 = add2(e2, nm), h3 = add2(e3, nm);
        f2 nrm2 = fma2(h1, h1, fma2(h2, h2, mul2(h3, h3)));

        float n2l, n2h; un2(nrm2, n2l, n2h);
        n2l = fmaxf(n2l, 1e-20f); n2h = fmaxf(n2h, 1e-20f);
        float rnl = rsqrtf(n2l), rnh = rsqrtf(n2h);
        float nrml = n2l * rnl, nrmh = n2h * rnh;

        f2 st = add2(tr, bc2(-3.0f * coh));
        float stl, sth; un2(st, stl, sth);
        float kl = fmaxf(nrml + coef * stl, 0.0f) * rnl;
        float kh = fmaxf(nrmh + coef * sth, 0.0f) * rnh;
        f2 nk = mk2(-kl, -kh);
        f2 ce1 = fma2(nk, h1, e1);
        f2 ce2 = fma2(nk, h2, e2);
        f2 ce3 = fma2(nk, h3, e3);

        float c1l, c1h, c2lo, c2hi, c3l, c3h;
        un2(ce1, c1l, c1h); un2(ce2, c2lo, c2hi); un2(ce3, c3l, c3h);
        bool yl = stl < 0.0f, yh = sth < 0.0f;
        f2 w1 = mk2(__expf(yl ? c1l : coh) * i1l, __expf(yh ? c1h : coh) * i1h);
        f2 w2 = mk2(__expf(yl ? c2lo : coh) * i2l, __expf(yh ? c2hi : coh) * i2h);
        f2 w3 = mk2(__expf(yl ? c3l : coh) * i3l, __expf(yh ? c3h : coh) * i3h);

        // F_corrected = sum_j w_j * b_j * v_j^T
        f2 p11 = mul2(b11, w1), p12 = mul2(b12, w2), p13 = mul2(b13, w3);
        f2 p21 = mul2(b21, w1), p22 = mul2(b22, w2), p23 = mul2(b23, w3);
        f2 p31 = mul2(b31, w1), p32 = mul2(b32, w2), p33 = mul2(b33, w3);

        f2 o0 = fma2(p11, v11, fma2(p12, v12, mul2(p13, v13)));
        f2 o1 = fma2(p11, v21, fma2(p12, v22, mul2(p13, v23)));
        f2 o2 = fma2(p11, v31, fma2(p12, v32, mul2(p13, v33)));
        f2 o3 = fma2(p21, v11, fma2(p22, v12, mul2(p23, v13)));
        f2 o4 = fma2(p21, v21, fma2(p22, v22, mul2(p23, v23)));
        f2 o5 = fma2(p21, v31, fma2(p22, v32, mul2(p23, v33)));
        f2 o6 = fma2(p31, v11, fma2(p32, v12, mul2(p33, v13)));
        f2 o7 = fma2(p31, v21, fma2(p32, v22, mul2(p33, v23)));
        f2 o8 = fma2(p31, v31, fma2(p32, v32, mul2(p33, v33)));

        // write results back into this chain's own smem slots (only this
        // thread ever touches them -> no barrier needed between chains)
        float* O0 = sm + (tid + 2 * c * BLOCK) * 9;
        float* O1 = sm + (tid + (2 * c + 1) * BLOCK) * 9;
        float lo, hi;
        un2(o0, lo, hi); O0[0] = lo; O1[0] = hi;
        un2(o1, lo, hi); O0[1] = lo; O1[1] = hi;
        un2(o2, lo, hi); O0[2] = lo; O1[2] = hi;
        un2(o3, lo, hi); O0[3] = lo; O1[3] = hi;
        un2(o4, lo, hi); O0[4] = lo; O1[4] = hi;
        un2(o5, lo, hi); O0[5] = lo; O1[5] = hi;
        un2(o6, lo, hi); O0[6] = lo; O1[6] = hi;
        un2(o7, lo, hi); O0[7] = lo; O1[7] = hi;
        un2(o8, lo, hi); O0[8] = lo; O1[8] = hi;
    }
    __syncthreads();

    // ---- coalesced store: smem -> global ----
    if (cnt == MPB) {
        float4* gv = (float4*)(out + (size_t)base * 9);
        const float4* sv = (const float4*)sm;
        #pragma unroll
        for (int k = tid; k < MPB * 9 / 4; k += BLOCK) gv[k] = sv[k];
    } else {
        float* g = out + (size_t)base * 9;
        for (int k = tid; k < nflt; k += BLOCK) g[k] = sm[k];
    }
}

extern "C" void kernel_launch(void* const* d_in, const int* in_sizes, int n_in,
                              void* d_out, int out_size) {
    const float* F    = (const float*)d_in[0];
    const float* ylog = (const float*)d_in[1];
    const float* nu   = (const float*)d_in[2];
    const float* phi  = (const float*)d_in[3];
    const float* coh  = (const float*)d_in[4];
    float* out = (float*)d_out;
    int n = in_sizes[0] / 9;
    int grid = (n + MPB - 1) / MPB;
    dp_plasticity_kernel<<<grid, BLOCK>>>(F, ylog, nu, phi, coh, out, n);
}

// round 7
// speedup vs baseline: 1.6600x; 1.2239x over previous
#include <cuda_runtime.h>
#include <cuda_bf16.h>
#include <math.h>

#define DEG2RAD 0.017453292519943295f
#define SIGMA_MIN 0.05f

#define BLOCK 128
#define MPB   (2 * BLOCK)   // matrices per block

typedef unsigned long long u64;
struct f2 { u64 v; };

__device__ __forceinline__ f2 mk2(float lo, float hi) {
    f2 r; asm("mov.b64 %0, {%1, %2};" : "=l"(r.v) : "f"(lo), "f"(hi)); return r;
}
__device__ __forceinline__ f2 bc2(float x) { return mk2(x, x); }
__device__ __forceinline__ void un2(f2 a, float &lo, float &hi) {
    asm("mov.b64 {%0, %1}, %2;" : "=f"(lo), "=f"(hi) : "l"(a.v));
}
__device__ __forceinline__ f2 add2(f2 a, f2 b) {
    f2 r; asm("add.rn.f32x2 %0, %1, %2;" : "=l"(r.v) : "l"(a.v), "l"(b.v)); return r;
}
__device__ __forceinline__ f2 mul2(f2 a, f2 b) {
    f2 r; asm("mul.rn.f32x2 %0, %1, %2;" : "=l"(r.v) : "l"(a.v), "l"(b.v)); return r;
}
__device__ __forceinline__ f2 fma2(f2 a, f2 b, f2 c) {
    f2 r; asm("fma.rn.f32x2 %0, %1, %2, %3;" : "=l"(r.v) : "l"(a.v), "l"(b.v), "l"(c.v)); return r;
}
__device__ __forceinline__ f2 neg2(f2 a) {
    f2 r; u64 m = 0x8000000080000000ULL;
    asm("xor.b64 %0, %1, %2;" : "=l"(r.v) : "l"(a.v), "l"(m)); return r;
}
__device__ __forceinline__ f2 abs2(f2 a) {
    f2 r; u64 m = 0x7fffffff7fffffffULL;
    asm("and.b64 %0, %1, %2;" : "=l"(r.v) : "l"(a.v), "l"(m)); return r;
}
__device__ __forceinline__ f2 sgn2(f2 a) {   // sign bits only
    f2 r; u64 m = 0x8000000080000000ULL;
    asm("and.b64 %0, %1, %2;" : "=l"(r.v) : "l"(a.v), "l"(m)); return r;
}
__device__ __forceinline__ f2 xor2(f2 a, f2 b) {
    f2 r; asm("xor.b64 %0, %1, %2;" : "=l"(r.v) : "l"(a.v), "l"(b.v)); return r;
}

// Exact-annihilation Jacobi rotation, NO-SWAP convention (|theta| <= pi/4).
// cos(2t) = |d|/r  in [0,1]  ->  cos^2(t) = (1+|d|/r)/2 in [1/2,1]: never
// degenerate, no cancellation. sign(d) folded into sin(t) and the diagonal
// update (s11' = m + sign(d)*r/2), so s11 keeps the eigenvalue nearest its
// original value (no swap -> stable for s21 -> 0 with either diagonal order).
// Roles: s11=S_pp, s21=S_qp (annihilated, NOT written), s22=S_qq,
//        s31=S_tp, s32=S_tq. V cols (va,vb) = (p,q).
template <bool S31_ZERO>
__device__ __forceinline__ void jx(
    f2 &s11, f2 &s21, f2 &s22, f2 &s31, f2 &s32,
    f2 &va1, f2 &va2, f2 &va3,
    f2 &vb1, f2 &vb2, f2 &vb3)
{
    const f2 HALF = bc2(0.5f);
    const f2 CM1  = bc2(-1.0f);

    f2 d  = fma2(s22, CM1, s11);          // s11 - s22
    f2 ad = abs2(d);
    f2 sg = sgn2(d);
    f2 ts = add2(s21, s21);
    f2 r2 = fma2(d, d, mul2(ts, ts));     // d^2 + 4 s21^2

    float r2l, r2h; un2(r2, r2l, r2h);
    float wl = rsqrtf(fmaxf(r2l, 1e-30f));
    float wh = rsqrtf(fmaxf(r2h, 1e-30f));
    f2 w = mk2(wl, wh);

    f2 c2t = mul2(ad, w);                 // |cos 2t| in [0,1]
    f2 a2  = fma2(c2t, HALF, HALF);       // cos^2 t in [1/2,1]
    float a2l, a2h; un2(a2, a2l, a2h);
    f2 ia = mk2(rsqrtf(a2l), rsqrtf(a2h));
    f2 aa = mul2(a2, ia);                 // cos t in [sqrt(1/2),1]
    f2 bb = mul2(mul2(xor2(s21, sg), w), ia);  // sin t = sign(d)*s21*w/cos t

    // true degeneracy (d ~ 0 and s21 ~ 0): identity rotation
    bool degl = r2l < 1e-24f;
    bool degh = r2h < 1e-24f;
    if (degl || degh) {
        float aal, aah, bbl, bbh;
        un2(aa, aal, aah); un2(bb, bbl, bbh);
        aa = mk2(degl ? 1.0f : aal, degh ? 1.0f : aah);
        bb = mk2(degl ? 0.0f : bbl, degh ? 0.0f : bbh);
    }

    // diagonal, closed form: s11' = m + sign(d)*r/2
    f2 rh  = mul2(mul2(r2, w), HALF);     // r/2
    f2 rhs = xor2(rh, sg);                // sign(d)*r/2
    f2 m   = mul2(add2(s11, s22), HALF);
    s11 = add2(m, rhs);
    s22 = add2(m, neg2(rhs));

    // third row/col rotate
    f2 nbb = neg2(bb);
    if (S31_ZERO) {
        f2 o32 = mul2(aa, s32);
        s31 = mul2(bb, s32);
        s32 = o32;
    } else {
        f2 o31 = fma2(aa, s31, mul2(bb, s32));
        f2 o32 = fma2(nbb, s31, mul2(aa, s32));
        s31 = o31; s32 = o32;
    }

    // V column rotate
    f2 t;
    t = fma2(aa, va1, mul2(bb, vb1)); vb1 = fma2(nbb, va1, mul2(aa, vb1)); va1 = t;
    t = fma2(aa, va2, mul2(bb, vb2)); vb2 = fma2(nbb, va2, mul2(aa, vb2)); va2 = t;
    t = fma2(aa, va3, mul2(bb, vb3)); vb3 = fma2(nbb, va3, mul2(aa, vb3)); va3 = t;
}

__global__ void __launch_bounds__(BLOCK)
dp_plasticity_kernel(const float* __restrict__ F,
                     const float* __restrict__ ylog_p,
                     const float* __restrict__ nu_p,
                     const float* __restrict__ phi_p,
                     const float* __restrict__ coh_p,
                     float* __restrict__ out, int n) {
    __shared__ float sm[MPB * 9];

    const int tid  = threadIdx.x;
    const int base = blockIdx.x * MPB;
    const int cnt  = min(MPB, n - base);
    const int nflt = cnt * 9;

    // ---- coalesced load: global -> smem (linear layout) ----
    if (cnt == MPB) {
        const float4* gv = (const float4*)(F + (size_t)base * 9);
        float4* sv = (float4*)sm;
        #pragma unroll
        for (int k = tid; k < MPB * 9 / 4; k += BLOCK) sv[k] = gv[k];
    } else {
        const float* g = F + (size_t)base * 9;
        for (int k = tid; k < nflt; k += BLOCK) sm[k] = g[k];
        for (int k = nflt + tid; k < MPB * 9; k += BLOCK) sm[k] = 1.0f;
    }
    __syncthreads();

    {
        const float* A0 = sm + tid * 9;
        const float* A1 = sm + (tid + BLOCK) * 9;
        f2 a11 = mk2(A0[0], A1[0]);
        f2 a12 = mk2(A0[1], A1[1]);
        f2 a13 = mk2(A0[2], A1[2]);
        f2 a21 = mk2(A0[3], A1[3]);
        f2 a22 = mk2(A0[4], A1[4]);
        f2 a23 = mk2(A0[5], A1[5]);
        f2 a31 = mk2(A0[6], A1[6]);
        f2 a32 = mk2(A0[7], A1[7]);
        f2 a33 = mk2(A0[8], A1[8]);

        // ---- S = A^T A ----
        f2 s11 = fma2(a11, a11, fma2(a21, a21, mul2(a31, a31)));
        f2 s21 = fma2(a11, a12, fma2(a21, a22, mul2(a31, a32)));
        f2 s22 = fma2(a12, a12, fma2(a22, a22, mul2(a32, a32)));
        f2 s31 = fma2(a11, a13, fma2(a21, a23, mul2(a31, a33)));
        f2 s32 = fma2(a12, a13, fma2(a22, a23, mul2(a32, a33)));
        f2 s33 = fma2(a13, a13, fma2(a23, a23, mul2(a33, a33)));

        // ---- V = I ----
        f2 v11 = bc2(1.0f), v12 = bc2(0.0f), v13 = bc2(0.0f);
        f2 v21 = bc2(0.0f), v22 = bc2(1.0f), v23 = bc2(0.0f);
        f2 v31 = bc2(0.0f), v32 = bc2(0.0f), v33 = bc2(1.0f);

        // ---- exact cyclic Jacobi, 3 sweeps (9 rotations) ----
        // pivot (1,2): roles s11,s21,s22 | third: s31,s32 | cols 1,2
        // pivot (2,3): roles s22,s32,s33 | third: s21,s31 | cols 2,3
        // pivot (3,1): roles s33,s31,s11 | third: s32,s21 | cols 3,1
        // The element annihilated by each step is the next step's "third-p"
        // slot, known to be zero -> S31_ZERO fast path.
        jx<false>(s11, s21, s22, s31, s32, v11, v21, v31, v12, v22, v32);
        jx<true >(s22, s32, s33, s21, s31, v12, v22, v32, v13, v23, v33);
        jx<true >(s33, s31, s11, s32, s21, v13, v23, v33, v11, v21, v31);
        #pragma unroll
        for (int sweep = 0; sweep < 2; sweep++) {
            jx<true>(s11, s21, s22, s31, s32, v11, v21, v31, v12, v22, v32);
            jx<true>(s22, s32, s33, s21, s31, v12, v22, v32, v13, v23, v33);
            jx<true>(s33, s31, s11, s32, s21, v13, v23, v33, v11, v21, v31);
        }

        // ---- material params (uniform scalars) ----
        float ylog = __ldg(ylog_p);
        float nu   = __ldg(nu_p);
        float phi  = __ldg(phi_p);
        float coh  = __ldg(coh_p);
        float E = __expf(ylog);
        float sinphi = __sinf(phi * DEG2RAD);
        float alpha = sqrtf(2.0f / 3.0f) * 2.0f * sinphi / (3.0f - sinphi);
        float mu = E / (2.0f * (1.0f + nu));
        float la = E * nu / ((1.0f + nu) * (1.0f - 2.0f * nu));
        float coef = (3.0f * la + 2.0f * mu) / (2.0f * mu) * alpha;

        // ---- B = A * V ; columns b_j = sigma_j * u_j ----
        f2 b11 = fma2(a11, v11, fma2(a12, v21, mul2(a13, v31)));
        f2 b12 = fma2(a11, v12, fma2(a12, v22, mul2(a13, v32)));
        f2 b13 = fma2(a11, v13, fma2(a12, v23, mul2(a13, v33)));
        f2 b21 = fma2(a21, v11, fma2(a22, v21, mul2(a23, v31)));
        f2 b22 = fma2(a21, v12, fma2(a22, v22, mul2(a23, v32)));
        f2 b23 = fma2(a21, v13, fma2(a22, v23, mul2(a23, v33)));
        f2 b31 = fma2(a31, v11, fma2(a32, v21, mul2(a33, v31)));
        f2 b32 = fma2(a31, v12, fma2(a32, v22, mul2(a33, v32)));
        f2 b33 = fma2(a31, v13, fma2(a32, v23, mul2(a33, v33)));

        // ---- sigma_j = ||b_j|| ----
        f2 rho1 = fma2(b11, b11, fma2(b21, b21, mul2(b31, b31)));
        f2 rho2 = fma2(b12, b12, fma2(b22, b22, mul2(b32, b32)));
        f2 rho3 = fma2(b13, b13, fma2(b23, b23, mul2(b33, b33)));

        float r1l, r1h, r2l, r2h, r3l, r3h;
        un2(rho1, r1l, r1h); un2(rho2, r2l, r2h); un2(rho3, r3l, r3h);
        float i1l = rsqrtf(fmaxf(r1l, 1e-30f)), i1h = rsqrtf(fmaxf(r1h, 1e-30f));
        float i2l = rsqrtf(fmaxf(r2l, 1e-30f)), i2h = rsqrtf(fmaxf(r2h, 1e-30f));
        float i3l = rsqrtf(fmaxf(r3l, 1e-30f)), i3h = rsqrtf(fmaxf(r3h, 1e-30f));
        float e1l = __logf(fmaxf(r1l * i1l, SIGMA_MIN)), e1h = __logf(fmaxf(r1h * i1h, SIGMA_MIN));
        float e2l = __logf(fmaxf(r2l * i2l, SIGMA_MIN)), e2h = __logf(fmaxf(r2h * i2h, SIGMA_MIN));
        float e3l = __logf(fmaxf(r3l * i3l, SIGMA_MIN)), e3h = __logf(fmaxf(r3h * i3h, SIGMA_MIN));

        f2 e1 = mk2(e1l, e1h), e2 = mk2(e2l, e2h), e3 = mk2(e3l, e3h);
        f2 tr = add2(e1, add2(e2, e3));
        f2 nm = mul2(tr, bc2(-1.0f / 3.0f));
        f2 h1 = add2(e1, nm), h2 = add2(e2, nm), h3 = add2(e3, nm);
        f2 nrm2 = fma2(h1, h1, fma2(h2, h2, mul2(h3, h3)));

        float n2l, n2h; un2(nrm2, n2l, n2h);
        n2l = fmaxf(n2l, 1e-20f); n2h = fmaxf(n2h, 1e-20f);
        float rnl = rsqrtf(n2l), rnh = rsqrtf(n2h);
        float nrml = n2l * rnl, nrmh = n2h * rnh;

        f2 st = add2(tr, bc2(-3.0f * coh));
        float stl, sth; un2(st, stl, sth);
        float kl = fmaxf(nrml + coef * stl, 0.0f) * rnl;
        float kh = fmaxf(nrmh + coef * sth, 0.0f) * rnh;
        f2 nk = mk2(-kl, -kh);
        f2 ce1 = fma2(nk, h1, e1);
        f2 ce2 = fma2(nk, h2, e2);
        f2 ce3 = fma2(nk, h3, e3);

        float c1l, c1h, c2lo, c2hi, c3l, c3h;
        un2(ce1, c1l, c1h); un2(ce2, c2lo, c2hi); un2(ce3, c3l, c3h);
        bool yl = stl < 0.0f, yh = sth < 0.0f;
        f2 w1 = mk2(__expf(yl ? c1l : coh) * i1l, __expf(yh ? c1h : coh) * i1h);
        f2 w2 = mk2(__expf(yl ? c2lo : coh) * i2l, __expf(yh ? c2hi : coh) * i2h);
        f2 w3 = mk2(__expf(yl ? c3l : coh) * i3l, __expf(yh ? c3h : coh) * i3h);

        // ---- F_corrected = sum_j w_j * b_j * v_j^T ----
        f2 p11 = mul2(b11, w1), p12 = mul2(b12, w2), p13 = mul2(b13, w3);
        f2 p21 = mul2(b21, w1), p22 = mul2(b22, w2), p23 = mul2(b23, w3);
        f2 p31 = mul2(b31, w1), p32 = mul2(b32, w2), p33 = mul2(b33, w3);

        f2 o0 = fma2(p11, v11, fma2(p12, v12, mul2(p13, v13)));
        f2 o1 = fma2(p11, v21, fma2(p12, v22, mul2(p13, v23)));
        f2 o2 = fma2(p11, v31, fma2(p12, v32, mul2(p13, v33)));
        f2 o3 = fma2(p21, v11, fma2(p22, v12, mul2(p23, v13)));
        f2 o4 = fma2(p21, v21, fma2(p22, v22, mul2(p23, v23)));
        f2 o5 = fma2(p21, v31, fma2(p22, v32, mul2(p23, v33)));
        f2 o6 = fma2(p31, v11, fma2(p32, v12, mul2(p33, v13)));
        f2 o7 = fma2(p31, v21, fma2(p32, v22, mul2(p33, v23)));
        f2 o8 = fma2(p31, v31, fma2(p32, v32, mul2(p33, v33)));

        __syncthreads();   // staging buffer reuse
        float* O0 = sm + tid * 9;
        float* O1 = sm + (tid + BLOCK) * 9;
        float lo, hi;
        un2(o0, lo, hi); O0[0] = lo; O1[0] = hi;
        un2(o1, lo, hi); O0[1] = lo; O1[1] = hi;
        un2(o2, lo, hi); O0[2] = lo; O1[2] = hi;
        un2(o3, lo, hi); O0[3] = lo; O1[3] = hi;
        un2(o4, lo, hi); O0[4] = lo; O1[4] = hi;
        un2(o5, lo, hi); O0[5] = lo; O1[5] = hi;
        un2(o6, lo, hi); O0[6] = lo; O1[6] = hi;
        un2(o7, lo, hi); O0[7] = lo; O1[7] = hi;
        un2(o8, lo, hi); O0[8] = lo; O1[8] = hi;
    }
    __syncthreads();

    // ---- coalesced store: smem -> global ----
    if (cnt == MPB) {
        float4* gv = (float4*)(out + (size_t)base * 9);
        const float4* sv = (const float4*)sm;
        #pragma unroll
        for (int k = tid; k < MPB * 9 / 4; k += BLOCK) gv[k] = sv[k];
    } else {
        float* g = out + (size_t)base * 9;
        for (int k = tid; k < nflt; k += BLOCK) g[k] = sm[k];
    }
}

extern "C" void kernel_launch(void* const* d_in, const int* in_sizes, int n_in,
                              void* d_out, int out_size) {
    const float* F    = (const float*)d_in[0];
    const float* ylog = (const float*)d_in[1];
    const float* nu   = (const float*)d_in[2];
    const float* phi  = (const float*)d_in[3];
    const float* coh  = (const float*)d_in[4];
    float* out = (float*)d_out;
    int n = in_sizes[0] / 9;
    int grid = (n + MPB - 1) / MPB;
    dp_plasticity_kernel<<<grid, BLOCK>>>(F, ylog, nu, phi, coh, out, n);
}

// round 9
// speedup vs baseline: 1.7581x; 1.0591x over previous
#include <cuda_runtime.h>
#include <cuda_bf16.h>
#include <math.h>

#define DEG2RAD 0.017453292519943295f
#define SIGMA_MIN 0.05f

#define BLOCK 128
#define MPB   (2 * BLOCK)   // matrices per block

typedef unsigned long long u64;
struct f2 { u64 v; };

__device__ __forceinline__ f2 mk2(float lo, float hi) {
    f2 r; asm("mov.b64 %0, {%1, %2};" : "=l"(r.v) : "f"(lo), "f"(hi)); return r;
}
__device__ __forceinline__ f2 bc2(float x) { return mk2(x, x); }
__device__ __forceinline__ void un2(f2 a, float &lo, float &hi) {
    asm("mov.b64 {%0, %1}, %2;" : "=f"(lo), "=f"(hi) : "l"(a.v));
}
__device__ __forceinline__ f2 add2(f2 a, f2 b) {
    f2 r; asm("add.rn.f32x2 %0, %1, %2;" : "=l"(r.v) : "l"(a.v), "l"(b.v)); return r;
}
__device__ __forceinline__ f2 mul2(f2 a, f2 b) {
    f2 r; asm("mul.rn.f32x2 %0, %1, %2;" : "=l"(r.v) : "l"(a.v), "l"(b.v)); return r;
}
__device__ __forceinline__ f2 fma2(f2 a, f2 b, f2 c) {
    f2 r; asm("fma.rn.f32x2 %0, %1, %2, %3;" : "=l"(r.v) : "l"(a.v), "l"(b.v), "l"(c.v)); return r;
}
__device__ __forceinline__ f2 neg2(f2 a) {
    f2 r; u64 m = 0x8000000080000000ULL;
    asm("xor.b64 %0, %1, %2;" : "=l"(r.v) : "l"(a.v), "l"(m)); return r;
}
__device__ __forceinline__ f2 abs2(f2 a) {
    f2 r; u64 m = 0x7fffffff7fffffffULL;
    asm("and.b64 %0, %1, %2;" : "=l"(r.v) : "l"(a.v), "l"(m)); return r;
}
__device__ __forceinline__ f2 sgn2(f2 a) {   // sign bits only
    f2 r; u64 m = 0x8000000080000000ULL;
    asm("and.b64 %0, %1, %2;" : "=l"(r.v) : "l"(a.v), "l"(m)); return r;
}
__device__ __forceinline__ f2 xor2(f2 a, f2 b) {
    f2 r; asm("xor.b64 %0, %1, %2;" : "=l"(r.v) : "l"(a.v), "l"(b.v)); return r;
}

// Exact-annihilation Jacobi rotation, NO-SWAP convention (|theta| <= pi/4),
// BRANCH-FREE: w = rsqrt(r2 + 1e-28) regularizes the fully-degenerate pivot
// smoothly (unit rotation to rel. err eps/r2; only deviates when the pivot is
// already diagonal to ~1e-13 relative, where the rotation is output-
// irrelevant). cos(2t) = |d|*w in [0,1) -> cos^2(t) in [1/2,1]: never
// degenerate, no clamps, no selects.
// Roles: s11=S_pp, s21=S_qp (annihilated, NOT written), s22=S_qq,
//        s31=S_tp, s32=S_tq. V cols (va,vb) = (p,q).
template <bool S31_ZERO>
__device__ __forceinline__ void jx(
    f2 &s11, f2 &s21, f2 &s22, f2 &s31, f2 &s32,
    f2 &va1, f2 &va2, f2 &va3,
    f2 &vb1, f2 &vb2, f2 &vb3)
{
    const f2 HALF = bc2(0.5f);
    const f2 CM1  = bc2(-1.0f);
    const f2 EPS  = bc2(1e-28f);

    f2 d  = fma2(s22, CM1, s11);          // s11 - s22
    f2 ad = abs2(d);
    f2 sg = sgn2(d);
    f2 ts = add2(s21, s21);
    f2 r2 = fma2(d, d, fma2(ts, ts, EPS));// d^2 + 4 s21^2 + eps

    float r2l, r2h; un2(r2, r2l, r2h);
    f2 w = mk2(rsqrtf(r2l), rsqrtf(r2h));

    f2 c2t = mul2(ad, w);                 // |cos 2t| in [0,1)
    f2 a2  = fma2(c2t, HALF, HALF);       // cos^2 t in [1/2,1]
    float a2l, a2h; un2(a2, a2l, a2h);
    f2 ia = mk2(rsqrtf(a2l), rsqrtf(a2h));
    f2 aa = mul2(a2, ia);                 // cos t in [sqrt(1/2),1]
    f2 bb = mul2(mul2(xor2(s21, sg), w), ia);  // sin t = sign(d)*s21*w/cos t

    // diagonal, closed form: s11' = m + sign(d)*r/2
    f2 rh  = mul2(mul2(r2, w), HALF);     // r/2
    f2 rhs = xor2(rh, sg);                // sign(d)*r/2
    f2 m   = mul2(add2(s11, s22), HALF);
    s11 = add2(m, rhs);
    s22 = add2(m, neg2(rhs));

    // third row/col rotate
    f2 nbb = neg2(bb);
    if (S31_ZERO) {
        f2 o32 = mul2(aa, s32);
        s31 = mul2(bb, s32);
        s32 = o32;
    } else {
        f2 o31 = fma2(aa, s31, mul2(bb, s32));
        f2 o32 = fma2(nbb, s31, mul2(aa, s32));
        s31 = o31; s32 = o32;
    }

    // V column rotate
    f2 t;
    t = fma2(aa, va1, mul2(bb, vb1)); vb1 = fma2(nbb, va1, mul2(aa, vb1)); va1 = t;
    t = fma2(aa, va2, mul2(bb, vb2)); vb2 = fma2(nbb, va2, mul2(aa, vb2)); va2 = t;
    t = fma2(aa, va3, mul2(bb, vb3)); vb3 = fma2(nbb, va3, mul2(aa, vb3)); va3 = t;
}

__global__ void __launch_bounds__(BLOCK)
dp_plasticity_kernel(const float* __restrict__ F,
                     const float* __restrict__ ylog_p,
                     const float* __restrict__ nu_p,
                     const float* __restrict__ phi_p,
                     const float* __restrict__ coh_p,
                     float* __restrict__ out, int n) {
    __shared__ float sm[MPB * 9];

    const int tid  = threadIdx.x;
    const int base = blockIdx.x * MPB;
    const int cnt  = min(MPB, n - base);
    const int nflt = cnt * 9;

    // ---- coalesced load: global -> smem (linear layout) ----
    if (cnt == MPB) {
        const float4* gv = (const float4*)(F + (size_t)base * 9);
        float4* sv = (float4*)sm;
        #pragma unroll
        for (int k = tid; k < MPB * 9 / 4; k += BLOCK) sv[k] = gv[k];
    } else {
        const float* g = F + (size_t)base * 9;
        for (int k = tid; k < nflt; k += BLOCK) sm[k] = g[k];
        for (int k = nflt + tid; k < MPB * 9; k += BLOCK) sm[k] = 1.0f;
    }
    __syncthreads();

    {
        const float* A0 = sm + tid * 9;
        const float* A1 = sm + (tid + BLOCK) * 9;
        f2 a11 = mk2(A0[0], A1[0]);
        f2 a12 = mk2(A0[1], A1[1]);
        f2 a13 = mk2(A0[2], A1[2]);
        f2 a21 = mk2(A0[3], A1[3]);
        f2 a22 = mk2(A0[4], A1[4]);
        f2 a23 = mk2(A0[5], A1[5]);
        f2 a31 = mk2(A0[6], A1[6]);
        f2 a32 = mk2(A0[7], A1[7]);
        f2 a33 = mk2(A0[8], A1[8]);

        // ---- S = A^T A ----
        f2 s11 = fma2(a11, a11, fma2(a21, a21, mul2(a31, a31)));
        f2 s21 = fma2(a11, a12, fma2(a21, a22, mul2(a31, a32)));
        f2 s22 = fma2(a12, a12, fma2(a22, a22, mul2(a32, a32)));
        f2 s31 = fma2(a11, a13, fma2(a21, a23, mul2(a31, a33)));
        f2 s32 = fma2(a12, a13, fma2(a22, a23, mul2(a32, a33)));
        f2 s33 = fma2(a13, a13, fma2(a23, a23, mul2(a33, a33)));

        // ---- V = I ----
        f2 v11 = bc2(1.0f), v12 = bc2(0.0f), v13 = bc2(0.0f);
        f2 v21 = bc2(0.0f), v22 = bc2(1.0f), v23 = bc2(0.0f);
        f2 v31 = bc2(0.0f), v32 = bc2(0.0f), v33 = bc2(1.0f);

        // ---- exact cyclic Jacobi, 3 sweeps (9 rotations) ----
        jx<false>(s11, s21, s22, s31, s32, v11, v21, v31, v12, v22, v32);
        jx<true >(s22, s32, s33, s21, s31, v12, v22, v32, v13, v23, v33);
        jx<true >(s33, s31, s11, s32, s21, v13, v23, v33, v11, v21, v31);
        #pragma unroll
        for (int sweep = 0; sweep < 2; sweep++) {
            jx<true>(s11, s21, s22, s31, s32, v11, v21, v31, v12, v22, v32);
            jx<true>(s22, s32, s33, s21, s31, v12, v22, v32, v13, v23, v33);
            jx<true>(s33, s31, s11, s32, s21, v13, v23, v33, v11, v21, v31);
        }

        // ---- material params (uniform scalars) ----
        float ylog = __ldg(ylog_p);
        float nu   = __ldg(nu_p);
        float phi  = __ldg(phi_p);
        float coh  = __ldg(coh_p);
        float E = __expf(ylog);
        float sinphi = __sinf(phi * DEG2RAD);
        float alpha = sqrtf(2.0f / 3.0f) * 2.0f * sinphi / (3.0f - sinphi);
        float mu = E / (2.0f * (1.0f + nu));
        float la = E * nu / ((1.0f + nu) * (1.0f - 2.0f * nu));
        float coef = (3.0f * la + 2.0f * mu) / (2.0f * mu) * alpha;

        // ---- B = A * V ; columns b_j = sigma_j * u_j ----
        f2 b11 = fma2(a11, v11, fma2(a12, v21, mul2(a13, v31)));
        f2 b12 = fma2(a11, v12, fma2(a12, v22, mul2(a13, v32)));
        f2 b13 = fma2(a11, v13, fma2(a12, v23, mul2(a13, v33)));
        f2 b21 = fma2(a21, v11, fma2(a22, v21, mul2(a23, v31)));
        f2 b22 = fma2(a21, v12, fma2(a22, v22, mul2(a23, v32)));
        f2 b23 = fma2(a21, v13, fma2(a22, v23, mul2(a23, v33)));
        f2 b31 = fma2(a31, v11, fma2(a32, v21, mul2(a33, v31)));
        f2 b32 = fma2(a31, v12, fma2(a32, v22, mul2(a33, v32)));
        f2 b33 = fma2(a31, v13, fma2(a32, v23, mul2(a33, v33)));

        // ---- sigma_j = ||b_j|| (self-normalizing: conditioning-safe) ----
        f2 rho1 = fma2(b11, b11, fma2(b21, b21, mul2(b31, b31)));
        f2 rho2 = fma2(b12, b12, fma2(b22, b22, mul2(b32, b32)));
        f2 rho3 = fma2(b13, b13, fma2(b23, b23, mul2(b33, b33)));

        float r1l, r1h, r2l, r2h, r3l, r3h;
        un2(rho1, r1l, r1h); un2(rho2, r2l, r2h); un2(rho3, r3l, r3h);
        float i1l = rsqrtf(fmaxf(r1l, 1e-30f)), i1h = rsqrtf(fmaxf(r1h, 1e-30f));
        float i2l = rsqrtf(fmaxf(r2l, 1e-30f)), i2h = rsqrtf(fmaxf(r2h, 1e-30f));
        float i3l = rsqrtf(fmaxf(r3l, 1e-30f)), i3h = rsqrtf(fmaxf(r3h, 1e-30f));
        float e1l = __logf(fmaxf(r1l * i1l, SIGMA_MIN)), e1h = __logf(fmaxf(r1h * i1h, SIGMA_MIN));
        float e2l = __logf(fmaxf(r2l * i2l, SIGMA_MIN)), e2h = __logf(fmaxf(r2h * i2h, SIGMA_MIN));
        float e3l = __logf(fmaxf(r3l * i3l, SIGMA_MIN)), e3h = __logf(fmaxf(r3h * i3h, SIGMA_MIN));

        f2 e1 = mk2(e1l, e1h), e2 = mk2(e2l, e2h), e3 = mk2(e3l, e3h);
        f2 tr = add2(e1, add2(e2, e3));
        f2 nm = mul2(tr, bc2(-1.0f / 3.0f));
        f2 h1 = add2(e1, nm), h2 = add2(e2, nm), h3 = add2(e3, nm);
        f2 nrm2 = fma2(h1, h1, fma2(h2, h2, mul2(h3, h3)));

        float n2l, n2h; un2(nrm2, n2l, n2h);
        n2l = fmaxf(n2l, 1e-20f); n2h = fmaxf(n2h, 1e-20f);
        float rnl = rsqrtf(n2l), rnh = rsqrtf(n2h);
        float nrml = n2l * rnl, nrmh = n2h * rnh;

        f2 st = add2(tr, bc2(-3.0f * coh));
        float stl, sth; un2(st, stl, sth);
        float kl = fmaxf(nrml + coef * stl, 0.0f) * rnl;
        float kh = fmaxf(nrmh + coef * sth, 0.0f) * rnh;
        f2 nk = mk2(-kl, -kh);
        f2 ce1 = fma2(nk, h1, e1);
        f2 ce2 = fma2(nk, h2, e2);
        f2 ce3 = fma2(nk, h3, e3);

        float c1l, c1h, c2lo, c2hi, c3l, c3h;
        un2(ce1, c1l, c1h); un2(ce2, c2lo, c2hi); un2(ce3, c3l, c3h);
        bool yl = stl < 0.0f, yh = sth < 0.0f;
        f2 w1 = mk2(__expf(yl ? c1l : coh) * i1l, __expf(yh ? c1h : coh) * i1h);
        f2 w2 = mk2(__expf(yl ? c2lo : coh) * i2l, __expf(yh ? c2hi : coh) * i2h);
        f2 w3 = mk2(__expf(yl ? c3l : coh) * i3l, __expf(yh ? c3h : coh) * i3h);

        // ---- F_corrected = sum_j w_j * b_j * v_j^T ----
        f2 p11 = mul2(b11, w1), p12 = mul2(b12, w2), p13 = mul2(b13, w3);
        f2 p21 = mul2(b21, w1), p22 = mul2(b22, w2), p23 = mul2(b23, w3);
        f2 p31 = mul2(b31, w1), p32 = mul2(b32, w2), p33 = mul2(b33, w3);

        f2 o0 = fma2(p11, v11, fma2(p12, v12, mul2(p13, v13)));
        f2 o1 = fma2(p11, v21, fma2(p12, v22, mul2(p13, v23)));
        f2 o2 = fma2(p11, v31, fma2(p12, v32, mul2(p13, v33)));
        f2 o3 = fma2(p21, v11, fma2(p22, v12, mul2(p23, v13)));
        f2 o4 = fma2(p21, v21, fma2(p22, v22, mul2(p23, v23)));
        f2 o5 = fma2(p21, v31, fma2(p22, v32, mul2(p23, v33)));
        f2 o6 = fma2(p31, v11, fma2(p32, v12, mul2(p33, v13)));
        f2 o7 = fma2(p31, v21, fma2(p32, v22, mul2(p33, v23)));
        f2 o8 = fma2(p31, v31, fma2(p32, v32, mul2(p33, v33)));

        __syncthreads();   // staging buffer reuse
        float* O0 = sm + tid * 9;
        float* O1 = sm + (tid + BLOCK) * 9;
        float lo, hi;
        un2(o0, lo, hi); O0[0] = lo; O1[0] = hi;
        un2(o1, lo, hi); O0[1] = lo; O1[1] = hi;
        un2(o2, lo, hi); O0[2] = lo; O1[2] = hi;
        un2(o3, lo, hi); O0[3] = lo; O1[3] = hi;
        un2(o4, lo, hi); O0[4] = lo; O1[4] = hi;
        un2(o5, lo, hi); O0[5] = lo; O1[5] = hi;
        un2(o6, lo, hi); O0[6] = lo; O1[6] = hi;
        un2(o7, lo, hi); O0[7] = lo; O1[7] = hi;
        un2(o8, lo, hi); O0[8] = lo; O1[8] = hi;
    }
    __syncthreads();

    // ---- coalesced store: smem -> global ----
    if (cnt == MPB) {
        float4* gv = (float4*)(out + (size_t)base * 9);
        const float4* sv = (const float4*)sm;
        #pragma unroll
        for (int k = tid; k < MPB * 9 / 4; k += BLOCK) gv[k] = sv[k];
    } else {
        float* g = out + (size_t)base * 9;
        for (int k = tid; k < nflt; k += BLOCK) g[k] = sm[k];
    }
}

extern "C" void kernel_launch(void* const* d_in, const int* in_sizes, int n_in,
                              void* d_out, int out_size) {
    const float* F    = (const float*)d_in[0];
    const float* ylog = (const float*)d_in[1];
    const float* nu   = (const float*)d_in[2];
    const float* phi  = (const float*)d_in[3];
    const float* coh  = (const float*)d_in[4];
    float* out = (float*)d_out;
    int n = in_sizes[0] / 9;
    int grid = (n + MPB - 1) / MPB;
    dp_plasticity_kernel<<<grid, BLOCK>>>(F, ylog, nu, phi, coh, out, n);
}